// round 2
// baseline (speedup 1.0000x reference)
#include <cuda_runtime.h>
#include <stdint.h>

#define N_NODES 50000
#define N_EDGES 800000
#define D 64
#define N_LAYERS 12

// Scratch (allocation-free rule: __device__ globals)
__device__ float g_aggr[N_NODES * D];
__device__ float g_buf0[N_NODES * D];
__device__ float g_buf1[N_NODES * D];

// ---------------------------------------------------------------------------
// Scatter: aggr[dst] += x[src] * w   (16 threads per edge, float4 + red.v4)
// edge_index arrives as int32 (harness converts int64 -> int32).
// ---------------------------------------------------------------------------
__global__ void scatter_kernel(const float* __restrict__ x,
                               const int* __restrict__ ei,
                               const float* __restrict__ ew,
                               float* __restrict__ aggr) {
    int tid = blockIdx.x * blockDim.x + threadIdx.x;
    int e = tid >> 4;
    int p = tid & 15;
    if (e >= N_EDGES) return;
    int src = ei[e];
    int dst = ei[N_EDGES + e];
    float w = ew[e];
    float4 v = *reinterpret_cast<const float4*>(x + (size_t)src * D + p * 4);
    v.x *= w; v.y *= w; v.z *= w; v.w *= w;
    float* out = aggr + (size_t)dst * D + p * 4;
    unsigned long long gptr = (unsigned long long)__cvta_generic_to_global(out);
    asm volatile("red.global.add.v4.f32 [%0], {%1,%2,%3,%4};"
                 :: "l"(gptr), "f"(v.x), "f"(v.y), "f"(v.z), "f"(v.w)
                 : "memory");
}

// ---------------------------------------------------------------------------
// Update: xout = l2norm( concat(l2norm(aggr), x) @ W + b )
// Block: 128 nodes, 256 threads. Register-tiled GEMM 8 rows x 4 cols / thread.
// smem: W_s [128][64] + h_s [128][stride 129] (conflict-free transpose)
// ---------------------------------------------------------------------------
#define TB 128
#define HS 129
#define SMEM_BYTES ((128 * 64 + 128 * HS) * 4)

__global__ void __launch_bounds__(256, 1)
update_kernel(const float* __restrict__ aggr,
              const float* __restrict__ xin,
              const float* __restrict__ W,   // [2D][D] slice for this layer
              const float* __restrict__ b,   // [D]
              float* __restrict__ xout) {
    extern __shared__ float smem[];
    float* W_s = smem;            // 128*64
    float* h_s = smem + 128 * 64; // 128 * HS (k-major, r minor)

    int tid = threadIdx.x;

    // Load W slice (8192 floats) as float4, coalesced
    const float4* Wv = reinterpret_cast<const float4*>(W);
    float4* Wsv = reinterpret_cast<float4*>(W_s);
#pragma unroll
    for (int i = 0; i < 8; ++i)
        Wsv[tid + i * 256] = Wv[tid + i * 256];

    // Phase 1: per-node l2norm(aggr) and x, transposed into h_s[k][r]
    int warp = tid >> 5, lane = tid & 31;
#pragma unroll 1
    for (int i = 0; i < 16; ++i) {
        int r = warp * 16 + i;
        int node = blockIdx.x * TB + r;
        float a0 = 0.f, a1 = 0.f, x0 = 0.f, x1 = 0.f;
        if (node < N_NODES) {
            const float* ar = aggr + (size_t)node * D;
            const float* xr = xin + (size_t)node * D;
            a0 = ar[lane]; a1 = ar[lane + 32];
            x0 = xr[lane]; x1 = xr[lane + 32];
        }
        float ss = a0 * a0 + a1 * a1;
#pragma unroll
        for (int m = 16; m; m >>= 1) ss += __shfl_xor_sync(0xFFFFFFFFu, ss, m);
        float inv = 1.0f / fmaxf(sqrtf(ss), 1e-12f);
        h_s[lane * HS + r]        = a0 * inv;
        h_s[(lane + 32) * HS + r] = a1 * inv;
        h_s[(lane + 64) * HS + r] = x0;
        h_s[(lane + 96) * HS + r] = x1;
    }
    __syncthreads();

    // Phase 2: GEMM. thread (tx,ty): cols tx*4..+3, rows ty*8..+7
    int tx = tid & 15, ty = tid >> 4;
    float acc[8][4];
    float b0 = b[tx * 4 + 0], b1 = b[tx * 4 + 1];
    float b2 = b[tx * 4 + 2], b3 = b[tx * 4 + 3];
#pragma unroll
    for (int i = 0; i < 8; ++i) {
        acc[i][0] = b0; acc[i][1] = b1; acc[i][2] = b2; acc[i][3] = b3;
    }

    const float* hrow = h_s + ty * 8;
#pragma unroll 4
    for (int k = 0; k < 128; ++k) {
        float4 w4 = *reinterpret_cast<const float4*>(W_s + k * 64 + tx * 4);
        float hv[8];
#pragma unroll
        for (int i = 0; i < 8; ++i) hv[i] = hrow[k * HS + i];
#pragma unroll
        for (int i = 0; i < 8; ++i) {
            acc[i][0] += hv[i] * w4.x;
            acc[i][1] += hv[i] * w4.y;
            acc[i][2] += hv[i] * w4.z;
            acc[i][3] += hv[i] * w4.w;
        }
    }

    // Phase 3: per-row l2norm across the 16 threads sharing ty, then store
#pragma unroll
    for (int i = 0; i < 8; ++i) {
        int r = ty * 8 + i;
        int node = blockIdx.x * TB + r;
        float ss = acc[i][0] * acc[i][0] + acc[i][1] * acc[i][1]
                 + acc[i][2] * acc[i][2] + acc[i][3] * acc[i][3];
#pragma unroll
        for (int m = 8; m; m >>= 1) ss += __shfl_xor_sync(0xFFFFFFFFu, ss, m);
        float inv = 1.0f / fmaxf(sqrtf(ss), 1e-12f);
        if (node < N_NODES) {
            float4 o;
            o.x = acc[i][0] * inv; o.y = acc[i][1] * inv;
            o.z = acc[i][2] * inv; o.w = acc[i][3] * inv;
            *reinterpret_cast<float4*>(xout + (size_t)node * D + tx * 4) = o;
        }
    }
}

// ---------------------------------------------------------------------------
extern "C" void kernel_launch(void* const* d_in, const int* in_sizes, int n_in,
                              void* d_out, int out_size) {
    const float* x   = (const float*)d_in[0];
    const int* ei    = (const int*)d_in[1];
    const float* ew  = (const float*)d_in[2];
    const float* W   = (const float*)d_in[3];
    const float* b   = (const float*)d_in[4];
    float* out       = (float*)d_out;

    float *aggr, *buf0, *buf1;
    cudaGetSymbolAddress((void**)&aggr, g_aggr);
    cudaGetSymbolAddress((void**)&buf0, g_buf0);
    cudaGetSymbolAddress((void**)&buf1, g_buf1);

    cudaFuncSetAttribute(update_kernel,
                         cudaFuncAttributeMaxDynamicSharedMemorySize,
                         SMEM_BYTES);

    const int scatter_blocks = (N_EDGES * 16) / 256; // exact: 50000
    const int update_blocks = (N_NODES + TB - 1) / TB;

    const float* cur = x;
    for (int l = 0; l < N_LAYERS; ++l) {
        cudaMemsetAsync(aggr, 0, (size_t)N_NODES * D * sizeof(float), 0);
        scatter_kernel<<<scatter_blocks, 256>>>(cur, ei, ew, aggr);
        float* nxt = (l == N_LAYERS - 1) ? out : ((l & 1) ? buf1 : buf0);
        update_kernel<<<update_blocks, 256, SMEM_BYTES>>>(
            aggr, cur, W + (size_t)l * 2 * D * D, b + (size_t)l * D, nxt);
        cur = nxt;
    }
}

// round 3
// speedup vs baseline: 1.2189x; 1.2189x over previous
#include <cuda_runtime.h>
#include <stdint.h>

#define N_NODES 50000
#define N_EDGES 800000
#define D 64
#define N_LAYERS 12

__device__ float g_aggr[N_NODES * D];
__device__ float g_buf0[N_NODES * D];
__device__ float g_buf1[N_NODES * D];

// ---------------------------------------------------------------------------
// Scatter: aggr[dst] += x[src] * w   (16 threads per edge, float4 + red.v4)
// ---------------------------------------------------------------------------
__global__ void scatter_kernel(const float* __restrict__ x,
                               const int* __restrict__ ei,
                               const float* __restrict__ ew,
                               float* __restrict__ aggr) {
    int tid = blockIdx.x * blockDim.x + threadIdx.x;
    int e = tid >> 4;
    int p = tid & 15;
    if (e >= N_EDGES) return;
    int src = ei[e];
    int dst = ei[N_EDGES + e];
    float w = ew[e];
    float4 v = *reinterpret_cast<const float4*>(x + (size_t)src * D + p * 4);
    v.x *= w; v.y *= w; v.z *= w; v.w *= w;
    float* out = aggr + (size_t)dst * D + p * 4;
    unsigned long long gptr = (unsigned long long)__cvta_generic_to_global(out);
    asm volatile("red.global.add.v4.f32 [%0], {%1,%2,%3,%4};"
                 :: "l"(gptr), "f"(v.x), "f"(v.y), "f"(v.z), "f"(v.w)
                 : "memory");
}

// ---------------------------------------------------------------------------
// Update: xout = l2norm( concat(l2norm(aggr), x) @ W + b )
// Persistent grid-stride over 64-node tiles. 256 threads, 3 CTA/SM.
// h stored ROW-major in smem (stride 132) -> float4 LDS in GEMM loop.
// Also zeroes aggr rows after reading (replaces per-layer memset).
// ---------------------------------------------------------------------------
#define TB 64
#define HSTR 132
#define N_TILES ((N_NODES + TB - 1) / TB)   // 782
#define SMEM_BYTES ((128 * 64 + TB * HSTR) * 4)  // 66560 B

__global__ void __launch_bounds__(256, 3)
update_kernel(float* __restrict__ aggr,
              const float* __restrict__ xin,
              const float* __restrict__ W,   // [128][64] layer slice
              const float* __restrict__ b,   // [64]
              float* __restrict__ xout) {
    extern __shared__ float smem[];
    float* W_s = smem;             // 128*64
    float* h_s = smem + 128 * 64;  // TB rows x HSTR

    int tid = threadIdx.x;
    int lane = tid & 31;
    int warp = tid >> 5;

    // Load W slice (8192 floats) once per block
    {
        const float4* Wv = reinterpret_cast<const float4*>(W);
        float4* Wsv = reinterpret_cast<float4*>(W_s);
#pragma unroll
        for (int i = 0; i < 8; ++i)
            Wsv[tid + i * 256] = Wv[tid + i * 256];
    }

    // GEMM thread mapping: tx -> 4 cols, ty -> 4 rows
    int tx = tid & 15, ty = tid >> 4;
    float4 bias = *reinterpret_cast<const float4*>(b + tx * 4);

    // Phase-1 mapping: warp handles 8 nodes; lane group of 4 per node
    int p1_node = (warp << 3) + (lane >> 2);  // 0..63 local row
    int p1_p = lane & 3;                      // 0..3 -> 16 floats each

    for (int tile = blockIdx.x; tile < N_TILES; tile += gridDim.x) {
        __syncthreads();  // protect h_s reuse across tiles

        // ---- Phase 1: load aggr + x, l2norm(aggr), fill h_s row-major,
        //      and zero the aggr rows (replaces memset for next scatter)
        {
            int node = tile * TB + p1_node;
            float4 a[4], xv[4];
            if (node < N_NODES) {
                const float4* ar = reinterpret_cast<const float4*>(aggr + (size_t)node * D);
                const float4* xr = reinterpret_cast<const float4*>(xin + (size_t)node * D);
#pragma unroll
                for (int j = 0; j < 4; ++j) {
                    a[j]  = ar[p1_p + j * 4];
                    xv[j] = xr[p1_p + j * 4];
                }
                // zero aggr row for next layer's scatter
                float4 z = make_float4(0.f, 0.f, 0.f, 0.f);
                float4* aw = reinterpret_cast<float4*>(aggr + (size_t)node * D);
#pragma unroll
                for (int j = 0; j < 4; ++j) aw[p1_p + j * 4] = z;
            } else {
#pragma unroll
                for (int j = 0; j < 4; ++j) {
                    a[j] = make_float4(0.f, 0.f, 0.f, 0.f);
                    xv[j] = a[j];
                }
            }
            float ss = 0.f;
#pragma unroll
            for (int j = 0; j < 4; ++j)
                ss += a[j].x * a[j].x + a[j].y * a[j].y
                    + a[j].z * a[j].z + a[j].w * a[j].w;
            ss += __shfl_xor_sync(0xFFFFFFFFu, ss, 1);
            ss += __shfl_xor_sync(0xFFFFFFFFu, ss, 2);
            float inv = 1.0f / fmaxf(sqrtf(ss), 1e-12f);

            float4* hr = reinterpret_cast<float4*>(h_s + p1_node * HSTR);
#pragma unroll
            for (int j = 0; j < 4; ++j) {
                float4 an;
                an.x = a[j].x * inv; an.y = a[j].y * inv;
                an.z = a[j].z * inv; an.w = a[j].w * inv;
                hr[p1_p + j * 4] = an;            // cols [0,64)
                hr[16 + p1_p + j * 4] = xv[j];     // cols [64,128)
            }
        }
        __syncthreads();

        // ---- Phase 2: GEMM 64x64 <- h[64][128] @ W[128][64]
        float acc[4][4];
#pragma unroll
        for (int i = 0; i < 4; ++i) {
            acc[i][0] = bias.x; acc[i][1] = bias.y;
            acc[i][2] = bias.z; acc[i][3] = bias.w;
        }
        const float* hbase = h_s + (ty * 4) * HSTR;
#pragma unroll 4
        for (int k = 0; k < 128; k += 4) {
            float4 w0 = *reinterpret_cast<const float4*>(W_s + (k + 0) * 64 + tx * 4);
            float4 w1 = *reinterpret_cast<const float4*>(W_s + (k + 1) * 64 + tx * 4);
            float4 w2 = *reinterpret_cast<const float4*>(W_s + (k + 2) * 64 + tx * 4);
            float4 w3 = *reinterpret_cast<const float4*>(W_s + (k + 3) * 64 + tx * 4);
#pragma unroll
            for (int i = 0; i < 4; ++i) {
                float4 h4 = *reinterpret_cast<const float4*>(hbase + i * HSTR + k);
                acc[i][0] += h4.x * w0.x; acc[i][1] += h4.x * w0.y;
                acc[i][2] += h4.x * w0.z; acc[i][3] += h4.x * w0.w;
                acc[i][0] += h4.y * w1.x; acc[i][1] += h4.y * w1.y;
                acc[i][2] += h4.y * w1.z; acc[i][3] += h4.y * w1.w;
                acc[i][0] += h4.z * w2.x; acc[i][1] += h4.z * w2.y;
                acc[i][2] += h4.z * w2.z; acc[i][3] += h4.z * w2.w;
                acc[i][0] += h4.w * w3.x; acc[i][1] += h4.w * w3.y;
                acc[i][2] += h4.w * w3.z; acc[i][3] += h4.w * w3.w;
            }
        }

        // ---- Phase 3: row l2norm across the 16 tx threads, store
#pragma unroll
        for (int i = 0; i < 4; ++i) {
            int r = ty * 4 + i;
            int node = tile * TB + r;
            float ss = acc[i][0] * acc[i][0] + acc[i][1] * acc[i][1]
                     + acc[i][2] * acc[i][2] + acc[i][3] * acc[i][3];
#pragma unroll
            for (int m = 8; m; m >>= 1) ss += __shfl_xor_sync(0xFFFFFFFFu, ss, m);
            float inv = 1.0f / fmaxf(sqrtf(ss), 1e-12f);
            if (node < N_NODES) {
                float4 o;
                o.x = acc[i][0] * inv; o.y = acc[i][1] * inv;
                o.z = acc[i][2] * inv; o.w = acc[i][3] * inv;
                *reinterpret_cast<float4*>(xout + (size_t)node * D + tx * 4) = o;
            }
        }
    }
}

// ---------------------------------------------------------------------------
extern "C" void kernel_launch(void* const* d_in, const int* in_sizes, int n_in,
                              void* d_out, int out_size) {
    const float* x  = (const float*)d_in[0];
    const int* ei   = (const int*)d_in[1];
    const float* ew = (const float*)d_in[2];
    const float* W  = (const float*)d_in[3];
    const float* b  = (const float*)d_in[4];
    float* out      = (float*)d_out;

    float *aggr, *buf0, *buf1;
    cudaGetSymbolAddress((void**)&aggr, g_aggr);
    cudaGetSymbolAddress((void**)&buf0, g_buf0);
    cudaGetSymbolAddress((void**)&buf1, g_buf1);

    cudaFuncSetAttribute(update_kernel,
                         cudaFuncAttributeMaxDynamicSharedMemorySize,
                         SMEM_BYTES);

    const int scatter_blocks = (N_EDGES * 16) / 256;
    const int update_blocks = 148 * 3;

    // One idempotent zero of aggr (updates re-zero it for following layers)
    cudaMemsetAsync(aggr, 0, (size_t)N_NODES * D * sizeof(float), 0);

    const float* cur = x;
    for (int l = 0; l < N_LAYERS; ++l) {
        scatter_kernel<<<scatter_blocks, 256>>>(cur, ei, ew, aggr);
        float* nxt = (l == N_LAYERS - 1) ? out : ((l & 1) ? buf1 : buf0);
        update_kernel<<<update_blocks, 256, SMEM_BYTES>>>(
            aggr, cur, W + (size_t)l * 2 * D * D, b + (size_t)l * D, nxt);
        cur = nxt;
    }
}